// round 5
// baseline (speedup 1.0000x reference)
#include <cuda_runtime.h>
#include <cuda_bf16.h>
#include <cstdint>

#define HID 256
#define TPB 32

typedef unsigned long long u64;
typedef unsigned int u32;

__device__ __forceinline__ u64 pk2(float a, float b) {
    u64 r; asm("mov.b64 %0, {%1, %2};" : "=l"(r) : "f"(a), "f"(b)); return r;
}
__device__ __forceinline__ void upk2(u64 v, float& lo, float& hi) {
    asm("mov.b64 {%0, %1}, %2;" : "=f"(lo), "=f"(hi) : "l"(v));
}
__device__ __forceinline__ u64 fma2(u64 a, u64 b, u64 c) {
    u64 d; asm("fma.rn.f32x2 %0, %1, %2, %3;" : "=l"(d) : "l"(a), "l"(b), "l"(c)); return d;
}
__device__ __forceinline__ u64 add2(u64 a, u64 b) {
    u64 d; asm("add.rn.f32x2 %0, %1, %2;" : "=l"(d) : "l"(a), "l"(b)); return d;
}
// full-precision path: 2x tanh.approx.f32 (2 MUFU ops)
__device__ __forceinline__ u64 tanh2(u64 v) {
    float lo, hi, tl, th;
    upk2(v, lo, hi);
    asm("tanh.approx.f32 %0, %1;" : "=f"(tl) : "f"(lo));
    asm("tanh.approx.f32 %0, %1;" : "=f"(th) : "f"(hi));
    return pk2(tl, th);
}
// fast path: pack to f16x2, one tanh.approx.f16x2 (1 MUFU op), unpack to f32
__device__ __forceinline__ u64 tanh2_h(u64 v) {
    float lo, hi;
    upk2(v, lo, hi);
    u32 hp;
    // d = {lo = 2nd operand, hi = 1st operand}
    asm("cvt.rn.f16x2.f32 %0, %1, %2;" : "=r"(hp) : "f"(hi), "f"(lo));
    u32 tp;
    asm("tanh.approx.f16x2 %0, %1;" : "=r"(tp) : "r"(hp));
    float tl, th;
    asm("{ .reg .b16 l, h;\n"
        "  mov.b32 {l, h}, %2;\n"
        "  cvt.f32.f16 %0, l;\n"
        "  cvt.f32.f16 %1, h; }"
        : "=f"(tl), "=f"(th) : "r"(tp));
    return pk2(tl, th);
}
__device__ __forceinline__ void lds2(u32 addr, u64& a, u64& b) {
    asm volatile("ld.shared.v2.u64 {%0, %1}, [%2];" : "=l"(a), "=l"(b) : "r"(addr));
}

// SMEM: per 2j-block, 10 u64 (80B):
//  [Ax0,Ay0, Bx0,By0, C0,Ax1, Ay1,Bx1, By1,C1]
//  Ax={W1[0][j]}x2  Ay={W1[1][j]}x2  Bx={b1[j]}x2  By={h*W2[j][0]}x2  C={h*W2[j][1]}x2
__shared__ u64 s_w[(HID / 2) * 10];

#define UNIT_F32(AX, AY, BX, BY, CC)                                   \
    {                                                                  \
        u64 pA = fma2(AX, y0A, fma2(AY, y1A, BX));                     \
        u64 pB = fma2(AX, y0B, fma2(AY, y1B, BX));                     \
        u64 tA = tanh2(pA);                                            \
        u64 tB = tanh2(pB);                                            \
        a0A = fma2(tA, BY, a0A);  a1A = fma2(tA, CC, a1A);             \
        a0B = fma2(tB, BY, a0B);  a1B = fma2(tB, CC, a1B);             \
    }

#define UNIT_F16(AX, AY, BX, BY, CC)                                   \
    {                                                                  \
        u64 pA = fma2(AX, y0A, fma2(AY, y1A, BX));                     \
        u64 pB = fma2(AX, y0B, fma2(AY, y1B, BX));                     \
        u64 tA = tanh2_h(pA);                                          \
        u64 tB = tanh2_h(pB);                                          \
        a0A = fma2(tA, BY, a0A);  a1A = fma2(tA, CC, a1A);             \
        a0B = fma2(tB, BY, a0B);  a1B = fma2(tB, CC, a1B);             \
    }

__device__ __forceinline__ void geval4(u64 y0A, u64 y1A, u64 y0B, u64 y1B,
                                       u32 wbase,
                                       u64 hb20p, u64 hb21p,
                                       u64& o0A, u64& o1A, u64& o0B, u64& o1B)
{
    u64 a0A = 0ull, a1A = 0ull, a0B = 0ull, a1B = 0ull;
    u32 addr = wbase;
    // 64 pairs of 2j-blocks. Even block: both units f16. Odd block: unit0 f32,
    // unit1 f16.  ->  f16 fraction = 0.75.
#pragma unroll 2
    for (int bp = 0; bp < (HID / 4); bp++, addr += 160) {
        u64 w0, w1, w2, w3, w4, w5, w6, w7, w8, w9;
        // even block
        lds2(addr,      w0, w1);
        lds2(addr + 16, w2, w3);
        lds2(addr + 32, w4, w5);
        lds2(addr + 48, w6, w7);
        lds2(addr + 64, w8, w9);
        UNIT_F16(w0, w1, w2, w3, w4);
        UNIT_F16(w5, w6, w7, w8, w9);
        // odd block
        lds2(addr + 80,  w0, w1);
        lds2(addr + 96,  w2, w3);
        lds2(addr + 112, w4, w5);
        lds2(addr + 128, w6, w7);
        lds2(addr + 144, w8, w9);
        UNIT_F32(w0, w1, w2, w3, w4);
        UNIT_F16(w5, w6, w7, w8, w9);
    }
    o0A = add2(a0A, hb20p);  o1A = add2(a1A, hb21p);
    o0B = add2(a0B, hb20p);  o1B = add2(a1B, hb21p);
}

__global__ __launch_bounds__(TPB)
void node_rk4_kernel(const float* __restrict__ x,
                     const float* __restrict__ W1,
                     const float* __restrict__ b1,
                     const float* __restrict__ W2,
                     const float* __restrict__ b2,
                     const float* __restrict__ Wf,
                     const float* __restrict__ bf,
                     const int*   __restrict__ tptr,
                     float* __restrict__ out,
                     int B)
{
    __shared__ float sc[8];
    __shared__ int   s_nsteps;

    const float h = 0.01f;
    const int tid = threadIdx.x;

    for (int j = tid; j < HID; j += TPB) {
        float wx = W1[j], wy = W1[HID + j], bb = b1[j];
        float wa = h * W2[2 * j], wb = h * W2[2 * j + 1];
        int base = (j >> 1) * 10 + (j & 1) * 5;
        s_w[base + 0] = pk2(wx, wx);
        s_w[base + 1] = pk2(wy, wy);
        s_w[base + 2] = pk2(bb, bb);
        s_w[base + 3] = pk2(wa, wa);
        s_w[base + 4] = pk2(wb, wb);
    }
    if (tid == 0) {
        sc[0] = h * b2[0]; sc[1] = h * b2[1];
        sc[2] = Wf[0]; sc[3] = Wf[1]; sc[4] = Wf[2]; sc[5] = Wf[3];
        sc[6] = bf[0]; sc[7] = bf[1];

        int tv = tptr[0];
        if (tv <= 0 || tv > 100000) tv = (int)__int_as_float(tv);
        double tf = 0.1 * (double)tv;
        double tt = 0.0;
        int n = 0;
        while (tt <= tf) { n++; tt += 0.01; }
        s_nsteps = n;
    }
    __syncthreads();

    u32 wbase = (u32)__cvta_generic_to_shared(s_w);

    const int q = blockIdx.x * TPB + tid;     // quad index: points 4q..4q+3
    const int nquads = B >> 2;
    if (q >= nquads) return;

    float4 xv0 = reinterpret_cast<const float4*>(x)[2 * q + 0];
    float4 xv1 = reinterpret_cast<const float4*>(x)[2 * q + 1];
    u64 y0A = pk2(xv0.x, xv0.z), y1A = pk2(xv0.y, xv0.w);
    u64 y0B = pk2(xv1.x, xv1.z), y1B = pk2(xv1.y, xv1.w);

    const int nsteps = s_nsteps;
    const u64 hb20p = pk2(sc[0], sc[0]);
    const u64 hb21p = pk2(sc[1], sc[1]);
    const u64 halfp = pk2(0.5f, 0.5f);
    const u64 twop  = pk2(2.0f, 2.0f);
    const u64 sixth = pk2(1.0f / 6.0f, 1.0f / 6.0f);

    for (int s = 0; s < nsteps; s++) {
        u64 k0A, k1A, k0B, k1B;
        u64 ac0A, ac1A, ac0B, ac1B;

        // k1
        geval4(y0A, y1A, y0B, y1B, wbase, hb20p, hb21p, k0A, k1A, k0B, k1B);
        ac0A = k0A; ac1A = k1A; ac0B = k0B; ac1B = k1B;

        // k2
        geval4(fma2(halfp, k0A, y0A), fma2(halfp, k1A, y1A),
               fma2(halfp, k0B, y0B), fma2(halfp, k1B, y1B),
               wbase, hb20p, hb21p, k0A, k1A, k0B, k1B);
        ac0A = fma2(twop, k0A, ac0A); ac1A = fma2(twop, k1A, ac1A);
        ac0B = fma2(twop, k0B, ac0B); ac1B = fma2(twop, k1B, ac1B);

        // k3
        geval4(fma2(halfp, k0A, y0A), fma2(halfp, k1A, y1A),
               fma2(halfp, k0B, y0B), fma2(halfp, k1B, y1B),
               wbase, hb20p, hb21p, k0A, k1A, k0B, k1B);
        ac0A = fma2(twop, k0A, ac0A); ac1A = fma2(twop, k1A, ac1A);
        ac0B = fma2(twop, k0B, ac0B); ac1B = fma2(twop, k1B, ac1B);

        // k4
        geval4(add2(y0A, k0A), add2(y1A, k1A),
               add2(y0B, k0B), add2(y1B, k1B),
               wbase, hb20p, hb21p, k0A, k1A, k0B, k1B);
        ac0A = add2(ac0A, k0A); ac1A = add2(ac1A, k1A);
        ac0B = add2(ac0B, k0B); ac1B = add2(ac1B, k1B);

        y0A = fma2(sixth, ac0A, y0A); y1A = fma2(sixth, ac1A, y1A);
        y0B = fma2(sixth, ac0B, y0B); y1B = fma2(sixth, ac1B, y1B);
    }

    const float wf00 = sc[2], wf01 = sc[3], wf10 = sc[4], wf11 = sc[5];
    const float bf0 = sc[6], bf1 = sc[7];

    float y0a, y0b, y1a, y1b, y0c, y0d, y1c, y1d;
    upk2(y0A, y0a, y0b);  upk2(y1A, y1a, y1b);
    upk2(y0B, y0c, y0d);  upk2(y1B, y1c, y1d);

    float4* outL = reinterpret_cast<float4*>(out);
    float4* outP = reinterpret_cast<float4*>(out + 2 * B);

    {
        float l0a = __fmaf_rn(y0a, wf00, __fmaf_rn(y1a, wf10, bf0));
        float l1a = __fmaf_rn(y0a, wf01, __fmaf_rn(y1a, wf11, bf1));
        float l0b = __fmaf_rn(y0b, wf00, __fmaf_rn(y1b, wf10, bf0));
        float l1b = __fmaf_rn(y0b, wf01, __fmaf_rn(y1b, wf11, bf1));
        float ma = fmaxf(l0a, l1a), mb = fmaxf(l0b, l1b);
        float e0a = __expf(l0a - ma), e1a = __expf(l1a - ma);
        float e0b = __expf(l0b - mb), e1b = __expf(l1b - mb);
        float ia = 1.0f / (e0a + e1a), ib = 1.0f / (e0b + e1b);
        outL[2 * q + 0] = make_float4(l0a, l1a, l0b, l1b);
        outP[2 * q + 0] = make_float4(e0a * ia, e1a * ia, e0b * ib, e1b * ib);
    }
    {
        float l0a = __fmaf_rn(y0c, wf00, __fmaf_rn(y1c, wf10, bf0));
        float l1a = __fmaf_rn(y0c, wf01, __fmaf_rn(y1c, wf11, bf1));
        float l0b = __fmaf_rn(y0d, wf00, __fmaf_rn(y1d, wf10, bf0));
        float l1b = __fmaf_rn(y0d, wf01, __fmaf_rn(y1d, wf11, bf1));
        float ma = fmaxf(l0a, l1a), mb = fmaxf(l0b, l1b);
        float e0a = __expf(l0a - ma), e1a = __expf(l1a - ma);
        float e0b = __expf(l0b - mb), e1b = __expf(l1b - mb);
        float ia = 1.0f / (e0a + e1a), ib = 1.0f / (e0b + e1b);
        outL[2 * q + 1] = make_float4(l0a, l1a, l0b, l1b);
        outP[2 * q + 1] = make_float4(e0a * ia, e1a * ia, e0b * ib, e1b * ib);
    }
}

extern "C" void kernel_launch(void* const* d_in, const int* in_sizes, int n_in,
                              void* d_out, int out_size)
{
    const float* x  = (const float*)d_in[0];
    const float* W1 = (const float*)d_in[1];
    const float* b1 = (const float*)d_in[2];
    const float* W2 = (const float*)d_in[3];
    const float* b2 = (const float*)d_in[4];
    const float* Wf = (const float*)d_in[5];
    const float* bf = (const float*)d_in[6];
    const int*   t  = (const int*)d_in[7];
    float* out = (float*)d_out;

    const int B = in_sizes[0] / 2;
    const int nquads = B / 4;
    const int grid = (nquads + TPB - 1) / TPB;
    node_rk4_kernel<<<grid, TPB>>>(x, W1, b1, W2, b2, Wf, bf, t, out, B);
}

// round 6
// speedup vs baseline: 1.1696x; 1.1696x over previous
#include <cuda_runtime.h>
#include <cuda_bf16.h>
#include <cstdint>

#define HID 256
#define TPB 32

typedef unsigned long long u64;
typedef unsigned int u32;

// ---- f32x2 helpers (RK4 state math stays in f32) ----
__device__ __forceinline__ u64 pk2(float a, float b) {
    u64 r; asm("mov.b64 %0, {%1, %2};" : "=l"(r) : "f"(a), "f"(b)); return r;
}
__device__ __forceinline__ void upk2(u64 v, float& lo, float& hi) {
    asm("mov.b64 {%0, %1}, %2;" : "=f"(lo), "=f"(hi) : "l"(v));
}
__device__ __forceinline__ u64 fma2(u64 a, u64 b, u64 c) {
    u64 d; asm("fma.rn.f32x2 %0, %1, %2, %3;" : "=l"(d) : "l"(a), "l"(b), "l"(c)); return d;
}
__device__ __forceinline__ u64 add2(u64 a, u64 b) {
    u64 d; asm("add.rn.f32x2 %0, %1, %2;" : "=l"(d) : "l"(a), "l"(b)); return d;
}

// ---- f16x2 helpers (inner g-eval datapath) ----
__device__ __forceinline__ u32 hfma2(u32 a, u32 b, u32 c) {
    u32 d; asm("fma.rn.f16x2 %0, %1, %2, %3;" : "=r"(d) : "r"(a), "r"(b), "r"(c)); return d;
}
__device__ __forceinline__ u32 htanh2(u32 a) {
    u32 d; asm("tanh.approx.f16x2 %0, %1;" : "=r"(d) : "r"(a)); return d;
}
// pack two f32 -> f16x2: lane0(lo)=a, lane1(hi)=b
__device__ __forceinline__ u32 f32pair_to_h2(float a, float b) {
    u32 d; asm("cvt.rn.f16x2.f32 %0, %1, %2;" : "=r"(d) : "f"(b), "f"(a)); return d;
}
// unpack f16x2 -> two f32
__device__ __forceinline__ void h2_to_f32pair(u32 v, float& lo, float& hi) {
    asm("{ .reg .b16 l, h;\n"
        "  mov.b32 {l, h}, %2;\n"
        "  cvt.f32.f16 %0, l;\n"
        "  cvt.f32.f16 %1, h; }"
        : "=f"(lo), "=f"(hi) : "r"(v));
}
__device__ __forceinline__ uint4 lds128(u32 addr) {
    uint4 q;
    asm volatile("ld.shared.v4.u32 {%0, %1, %2, %3}, [%4];"
                 : "=r"(q.x), "=r"(q.y), "=r"(q.z), "=r"(q.w) : "r"(addr));
    return q;
}
__device__ __forceinline__ u32 h2dup(float v) {
    u32 d; asm("cvt.rn.f16x2.f32 %0, %1, %1;" : "=r"(d) : "f"(v)); return d;
}

// one hidden unit j: 4 HFMA2 + 1 XU, serving 2 points (f16x2 lanes)
#define UNIT(AX, AY, BB, WA, WB, A0, A1)                 \
    {                                                    \
        u32 pre = hfma2(AX, h0, hfma2(AY, h1, BB));      \
        u32 t = htanh2(pre);                             \
        A0 = hfma2(t, WA, A0);                           \
        A1 = hfma2(t, WB, A1);                           \
    }

// SMEM weight layout: per 4j-superblock, 20 u32 (80B) = 5x LDS.128:
//  j0:{w1x,w1y,b1,w2a} j0:{w2b} j1:{w1x,w1y,b1} j1:{w2a,w2b} j2:{...} ...
// linear order: j0.f0..f4, j1.f0..f4, j2.f0..f4, j3.f0..f4
__device__ __forceinline__ void geval2h(u32 h0, u32 h1, u32 wbase,
                                        u64 hb20p, u64 hb21p,
                                        u64& o0, u64& o1)
{
    u32 a0A = 0u, a0B = 0u, a1A = 0u, a1B = 0u;  // f16x2 accumulators
    u32 addr = wbase;
#pragma unroll 4
    for (int blk = 0; blk < HID / 4; blk++, addr += 80) {
        uint4 q0 = lds128(addr);
        uint4 q1 = lds128(addr + 16);
        uint4 q2 = lds128(addr + 32);
        uint4 q3 = lds128(addr + 48);
        uint4 q4 = lds128(addr + 64);
        UNIT(q0.x, q0.y, q0.z, q0.w, q1.x, a0A, a1A);  // j0
        UNIT(q1.y, q1.z, q1.w, q2.x, q2.y, a0B, a1B);  // j1
        UNIT(q2.z, q2.w, q3.x, q3.y, q3.z, a0A, a1A);  // j2
        UNIT(q3.w, q4.x, q4.y, q4.z, q4.w, a0B, a1B);  // j3
    }
    float xl, xh, yl, yh;
    h2_to_f32pair(a0A, xl, xh);
    h2_to_f32pair(a0B, yl, yh);
    o0 = add2(pk2(xl + yl, xh + yh), hb20p);
    h2_to_f32pair(a1A, xl, xh);
    h2_to_f32pair(a1B, yl, yh);
    o1 = add2(pk2(xl + yl, xh + yh), hb21p);
}

__global__ __launch_bounds__(TPB)
void node_rk4_kernel(const float* __restrict__ x,
                     const float* __restrict__ W1,
                     const float* __restrict__ b1,
                     const float* __restrict__ W2,
                     const float* __restrict__ b2,
                     const float* __restrict__ Wf,
                     const float* __restrict__ bf,
                     const int*   __restrict__ tptr,
                     float* __restrict__ out,
                     int B)
{
    __shared__ u32   s_w[(HID / 4) * 20];
    __shared__ float sc[8];
    __shared__ int   s_nsteps;

    const float h = 0.01f;
    const int tid = threadIdx.x;

    for (int j = tid; j < HID; j += TPB) {
        float wx = W1[j], wy = W1[HID + j], bb = b1[j];
        float wa = h * W2[2 * j], wb = h * W2[2 * j + 1];
        int base = (j >> 2) * 20 + (j & 3) * 5;
        s_w[base + 0] = h2dup(wx);
        s_w[base + 1] = h2dup(wy);
        s_w[base + 2] = h2dup(bb);
        s_w[base + 3] = h2dup(wa);
        s_w[base + 4] = h2dup(wb);
    }
    if (tid == 0) {
        sc[0] = h * b2[0]; sc[1] = h * b2[1];
        sc[2] = Wf[0]; sc[3] = Wf[1]; sc[4] = Wf[2]; sc[5] = Wf[3];
        sc[6] = bf[0]; sc[7] = bf[1];

        int tv = tptr[0];
        if (tv <= 0 || tv > 100000) tv = (int)__int_as_float(tv);
        double tf = 0.1 * (double)tv;
        double tt = 0.0;
        int n = 0;
        while (tt <= tf) { n++; tt += 0.01; }
        s_nsteps = n;
    }
    __syncthreads();

    u32 wbase = (u32)__cvta_generic_to_shared(s_w);

    const int i = blockIdx.x * TPB + tid;     // pair index: points 2i, 2i+1
    const int npairs = B >> 1;
    if (i >= npairs) return;

    float4 xv = reinterpret_cast<const float4*>(x)[i];
    u64 y0p = pk2(xv.x, xv.z);   // comp0 of (ptA, ptB)
    u64 y1p = pk2(xv.y, xv.w);   // comp1 of (ptA, ptB)

    const int nsteps = s_nsteps;
    const u64 hb20p = pk2(sc[0], sc[0]);
    const u64 hb21p = pk2(sc[1], sc[1]);
    const u64 halfp = pk2(0.5f, 0.5f);
    const u64 twop  = pk2(2.0f, 2.0f);
    const u64 sixth = pk2(1.0f / 6.0f, 1.0f / 6.0f);

    for (int s = 0; s < nsteps; s++) {
        float e0, e1, f0, f1;
        u64 k0, k1, ac0, ac1, yt0, yt1;
        u32 h0, h1;

        // k1 at y
        upk2(y0p, e0, e1); upk2(y1p, f0, f1);
        h0 = f32pair_to_h2(e0, e1); h1 = f32pair_to_h2(f0, f1);
        geval2h(h0, h1, wbase, hb20p, hb21p, k0, k1);
        ac0 = k0; ac1 = k1;

        // k2 at y + k1/2
        yt0 = fma2(halfp, k0, y0p); yt1 = fma2(halfp, k1, y1p);
        upk2(yt0, e0, e1); upk2(yt1, f0, f1);
        h0 = f32pair_to_h2(e0, e1); h1 = f32pair_to_h2(f0, f1);
        geval2h(h0, h1, wbase, hb20p, hb21p, k0, k1);
        ac0 = fma2(twop, k0, ac0); ac1 = fma2(twop, k1, ac1);

        // k3 at y + k2/2
        yt0 = fma2(halfp, k0, y0p); yt1 = fma2(halfp, k1, y1p);
        upk2(yt0, e0, e1); upk2(yt1, f0, f1);
        h0 = f32pair_to_h2(e0, e1); h1 = f32pair_to_h2(f0, f1);
        geval2h(h0, h1, wbase, hb20p, hb21p, k0, k1);
        ac0 = fma2(twop, k0, ac0); ac1 = fma2(twop, k1, ac1);

        // k4 at y + k3
        yt0 = add2(y0p, k0); yt1 = add2(y1p, k1);
        upk2(yt0, e0, e1); upk2(yt1, f0, f1);
        h0 = f32pair_to_h2(e0, e1); h1 = f32pair_to_h2(f0, f1);
        geval2h(h0, h1, wbase, hb20p, hb21p, k0, k1);
        ac0 = add2(ac0, k0); ac1 = add2(ac1, k1);

        y0p = fma2(sixth, ac0, y0p);
        y1p = fma2(sixth, ac1, y1p);
    }

    const float wf00 = sc[2], wf01 = sc[3], wf10 = sc[4], wf11 = sc[5];
    const float bf0 = sc[6], bf1 = sc[7];

    float y0a, y0b, y1a, y1b;
    upk2(y0p, y0a, y0b);
    upk2(y1p, y1a, y1b);

    float l0a = __fmaf_rn(y0a, wf00, __fmaf_rn(y1a, wf10, bf0));
    float l1a = __fmaf_rn(y0a, wf01, __fmaf_rn(y1a, wf11, bf1));
    float l0b = __fmaf_rn(y0b, wf00, __fmaf_rn(y1b, wf10, bf0));
    float l1b = __fmaf_rn(y0b, wf01, __fmaf_rn(y1b, wf11, bf1));

    float ma = fmaxf(l0a, l1a), mb = fmaxf(l0b, l1b);
    float e0a = __expf(l0a - ma), e1a = __expf(l1a - ma);
    float e0b = __expf(l0b - mb), e1b = __expf(l1b - mb);
    float ia = 1.0f / (e0a + e1a), ib = 1.0f / (e0b + e1b);

    float4* outL = reinterpret_cast<float4*>(out);
    float4* outP = reinterpret_cast<float4*>(out + 2 * B);
    outL[i] = make_float4(l0a, l1a, l0b, l1b);
    outP[i] = make_float4(e0a * ia, e1a * ia, e0b * ib, e1b * ib);
}

extern "C" void kernel_launch(void* const* d_in, const int* in_sizes, int n_in,
                              void* d_out, int out_size)
{
    const float* x  = (const float*)d_in[0];
    const float* W1 = (const float*)d_in[1];
    const float* b1 = (const float*)d_in[2];
    const float* W2 = (const float*)d_in[3];
    const float* b2 = (const float*)d_in[4];
    const float* Wf = (const float*)d_in[5];
    const float* bf = (const float*)d_in[6];
    const int*   t  = (const int*)d_in[7];
    float* out = (float*)d_out;

    const int B = in_sizes[0] / 2;
    const int npairs = B / 2;
    const int grid = (npairs + TPB - 1) / TPB;
    node_rk4_kernel<<<grid, TPB>>>(x, W1, b1, W2, b2, Wf, bf, t, out, B);
}

// round 7
// speedup vs baseline: 1.3259x; 1.1337x over previous
#include <cuda_runtime.h>
#include <cuda_bf16.h>
#include <cstdint>

#define HID 256
#define TPB 128

typedef unsigned long long u64;
typedef unsigned int u32;

// ---- f16x2 helpers ----
__device__ __forceinline__ u32 hfma2(u32 a, u32 b, u32 c) {
    u32 d; asm("fma.rn.f16x2 %0, %1, %2, %3;" : "=r"(d) : "r"(a), "r"(b), "r"(c)); return d;
}
__device__ __forceinline__ u32 htanh2(u32 a) {
    u32 d; asm("tanh.approx.f16x2 %0, %1;" : "=r"(d) : "r"(a)); return d;
}
__device__ __forceinline__ u32 f32pair_to_h2(float a, float b) {
    u32 d; asm("cvt.rn.f16x2.f32 %0, %1, %2;" : "=r"(d) : "f"(b), "f"(a)); return d;
}
__device__ __forceinline__ void h2_to_f32pair(u32 v, float& lo, float& hi) {
    asm("{ .reg .b16 l, h;\n"
        "  mov.b32 {l, h}, %2;\n"
        "  cvt.f32.f16 %0, l;\n"
        "  cvt.f32.f16 %1, h; }"
        : "=f"(lo), "=f"(hi) : "r"(v));
}
__device__ __forceinline__ u32 h2dup(float v) {
    u32 d; asm("cvt.rn.f16x2.f32 %0, %1, %1;" : "=r"(d) : "f"(v)); return d;
}
__device__ __forceinline__ uint4 lds128(u32 addr) {
    uint4 q;
    asm volatile("ld.shared.v4.u32 {%0, %1, %2, %3}, [%4];"
                 : "=r"(q.x), "=r"(q.y), "=r"(q.z), "=r"(q.w) : "r"(addr));
    return q;
}

// one j-pair: pre = {pre_2p, pre_2p+1}; 3 HFMA2 + 1 XU + accumulate
#define JPAIR(WX, WY, BB, WA, WB, A0, A1)                \
    {                                                    \
        u32 pre = hfma2(WX, h0, hfma2(WY, h1, BB));      \
        u32 t = htanh2(pre);                             \
        A0 = hfma2(t, WA, A0);                           \
        A1 = hfma2(t, WB, A1);                           \
    }

// SMEM: per superblock (4 j-pairs = 8 hidden units), 20 u32 = 5x LDS.128:
//  pair p fields: {W1x_p, W1y_p, B1_p, W2a_p, W2b_p}, linear.
__device__ __forceinline__ void geval1(float y0, float y1, u32 wbase,
                                       float hb20, float hb21,
                                       float& o0, float& o1)
{
    u32 h0 = h2dup(y0);
    u32 h1 = h2dup(y1);
    u32 a0A = 0u, a0B = 0u, a1A = 0u, a1B = 0u;
    u32 addr = wbase;
#pragma unroll 4
    for (int blk = 0; blk < HID / 8; blk++, addr += 80) {
        uint4 q0 = lds128(addr);
        uint4 q1 = lds128(addr + 16);
        uint4 q2 = lds128(addr + 32);
        uint4 q3 = lds128(addr + 48);
        uint4 q4 = lds128(addr + 64);
        JPAIR(q0.x, q0.y, q0.z, q0.w, q1.x, a0A, a1A);
        JPAIR(q1.y, q1.z, q1.w, q2.x, q2.y, a0B, a1B);
        JPAIR(q2.z, q2.w, q3.x, q3.y, q3.z, a0A, a1A);
        JPAIR(q3.w, q4.x, q4.y, q4.z, q4.w, a0B, a1B);
    }
    float p, q, r, s;
    h2_to_f32pair(a0A, p, q);
    h2_to_f32pair(a0B, r, s);
    o0 = ((p + q) + (r + s)) + hb20;
    h2_to_f32pair(a1A, p, q);
    h2_to_f32pair(a1B, r, s);
    o1 = ((p + q) + (r + s)) + hb21;
}

__global__ __launch_bounds__(TPB)
void node_rk4_kernel(const float* __restrict__ x,
                     const float* __restrict__ W1,
                     const float* __restrict__ b1,
                     const float* __restrict__ W2,
                     const float* __restrict__ b2,
                     const float* __restrict__ Wf,
                     const float* __restrict__ bf,
                     const int*   __restrict__ tptr,
                     float* __restrict__ out,
                     int B)
{
    __shared__ u32   s_w[(HID / 8) * 20];
    __shared__ float sc[8];
    __shared__ int   s_nsteps;

    const float h = 0.01f;
    const int tid = threadIdx.x;

    // j-pair p covers hidden units 2p, 2p+1.  128 pairs; one per thread.
    if (tid < HID / 2) {
        int p = tid;
        int j0 = 2 * p, j1 = 2 * p + 1;
        u32 wx = f32pair_to_h2(W1[j0],        W1[j1]);
        u32 wy = f32pair_to_h2(W1[HID + j0],  W1[HID + j1]);
        u32 bb = f32pair_to_h2(b1[j0],        b1[j1]);
        u32 wa = f32pair_to_h2(h * W2[2 * j0],     h * W2[2 * j1]);
        u32 wb = f32pair_to_h2(h * W2[2 * j0 + 1], h * W2[2 * j1 + 1]);
        int base = (p >> 2) * 20 + (p & 3) * 5;
        s_w[base + 0] = wx;
        s_w[base + 1] = wy;
        s_w[base + 2] = bb;
        s_w[base + 3] = wa;
        s_w[base + 4] = wb;
    }
    if (tid == 0) {
        sc[0] = h * b2[0]; sc[1] = h * b2[1];
        sc[2] = Wf[0]; sc[3] = Wf[1]; sc[4] = Wf[2]; sc[5] = Wf[3];
        sc[6] = bf[0]; sc[7] = bf[1];

        int tv = tptr[0];
        if (tv <= 0 || tv > 100000) tv = (int)__int_as_float(tv);
        double tf = 0.1 * (double)tv;
        double tt = 0.0;
        int n = 0;
        while (tt <= tf) { n++; tt += 0.01; }
        s_nsteps = n;
    }
    __syncthreads();

    u32 wbase = (u32)__cvta_generic_to_shared(s_w);

    const int i = blockIdx.x * TPB + tid;
    if (i >= B) return;

    float2 xv = reinterpret_cast<const float2*>(x)[i];
    float y0 = xv.x, y1 = xv.y;

    const int nsteps = s_nsteps;
    const float hb20 = sc[0], hb21 = sc[1];

    for (int s = 0; s < nsteps; s++) {
        float k10, k11, k20, k21, k30, k31, k40, k41;
        geval1(y0, y1, wbase, hb20, hb21, k10, k11);
        geval1(__fmaf_rn(0.5f, k10, y0), __fmaf_rn(0.5f, k11, y1),
               wbase, hb20, hb21, k20, k21);
        geval1(__fmaf_rn(0.5f, k20, y0), __fmaf_rn(0.5f, k21, y1),
               wbase, hb20, hb21, k30, k31);
        geval1(y0 + k30, y1 + k31, wbase, hb20, hb21, k40, k41);

        y0 = __fmaf_rn((k10 + 2.0f * (k20 + k30) + k40), (1.0f / 6.0f), y0);
        y1 = __fmaf_rn((k11 + 2.0f * (k21 + k31) + k41), (1.0f / 6.0f), y1);
    }

    float l0 = __fmaf_rn(y0, sc[2], __fmaf_rn(y1, sc[4], sc[6]));
    float l1 = __fmaf_rn(y0, sc[3], __fmaf_rn(y1, sc[5], sc[7]));

    float m  = fmaxf(l0, l1);
    float e0 = __expf(l0 - m);
    float e1 = __expf(l1 - m);
    float inv = 1.0f / (e0 + e1);

    float2* outL = reinterpret_cast<float2*>(out);
    float2* outP = reinterpret_cast<float2*>(out + 2 * B);
    outL[i] = make_float2(l0, l1);
    outP[i] = make_float2(e0 * inv, e1 * inv);
}

extern "C" void kernel_launch(void* const* d_in, const int* in_sizes, int n_in,
                              void* d_out, int out_size)
{
    const float* x  = (const float*)d_in[0];
    const float* W1 = (const float*)d_in[1];
    const float* b1 = (const float*)d_in[2];
    const float* W2 = (const float*)d_in[3];
    const float* b2 = (const float*)d_in[4];
    const float* Wf = (const float*)d_in[5];
    const float* bf = (const float*)d_in[6];
    const int*   t  = (const int*)d_in[7];
    float* out = (float*)d_out;

    const int B = in_sizes[0] / 2;
    const int grid = (B + TPB - 1) / TPB;
    node_rk4_kernel<<<grid, TPB>>>(x, W1, b1, W2, b2, Wf, bf, t, out, B);
}